// round 2
// baseline (speedup 1.0000x reference)
#include <cuda_runtime.h>
#include <cfloat>
#include <cstdint>

#define BATCH 32
#define PTS   1024
#define KNN   20
#define NPTS  (BATCH*PTS)

// ---------------- device scratch (no allocations allowed) ----------------
__device__ int   g_idx1[NPTS*KNN];    // kNN in pos space
__device__ float g_x1  [NPTS*64];     // conv1 output
__device__ float g_x1sq[NPTS];        // |x1|^2 per point
__device__ int   g_idx2[NPTS*KNN];    // kNN in feature space
__device__ float g_z   [NPTS*128];    // x1_j @ Wb
__device__ float g_s   [NPTS*128];    // x1_i @ (Wt-Wb) + b
__device__ float g_x2  [NPTS*128];    // conv2 output

// ordered-uint encoding for float atomicMax (handles negatives)
__device__ __forceinline__ unsigned f2key(float f){
    unsigned u = __float_as_uint(f);
    return (u & 0x80000000u) ? ~u : (u | 0x80000000u);
}
__device__ __forceinline__ float key2f(unsigned u){
    unsigned b = (u & 0x80000000u) ? (u & 0x7FFFFFFFu) : ~u;
    return __uint_as_float(b);
}

// ---------------- kernel 0/7: init + decode output ----------------
__global__ void init_out_kernel(unsigned* out){
    int t = blockIdx.x*blockDim.x + threadIdx.x;
    if (t < BATCH*128) out[t] = 0u;   // encodes -inf
}
__global__ void decode_out_kernel(unsigned* out){
    int t = blockIdx.x*blockDim.x + threadIdx.x;
    if (t < BATCH*128) out[t] = __float_as_uint(key2f(out[t]));
}

// ---------------- kernel 1: kNN in 3D position space ----------------
__global__ __launch_bounds__(128) void knn_pos_kernel(const float* __restrict__ pos){
    __shared__ float xs[PTS], ys[PTS], zs[PTS];
    int cloud = blockIdx.y;
    int base  = cloud * PTS;
    for (int t = threadIdx.x; t < PTS; t += 128){
        xs[t] = pos[(base+t)*3+0];
        ys[t] = pos[(base+t)*3+1];
        zs[t] = pos[(base+t)*3+2];
    }
    __syncthreads();
    int il = blockIdx.x*128 + threadIdx.x;
    float xi = xs[il], yi = ys[il], zi = zs[il];

    float bd[KNN]; int bj[KNN];
    #pragma unroll
    for (int k=0;k<KNN;k++){ bd[k]=FLT_MAX; bj[k]=base+il; }
    float worst = FLT_MAX; int wpos = 0;

    for (int j=0;j<PTS;j++){
        float dx = xs[j]-xi, dy = ys[j]-yi, dz = zs[j]-zi;
        float d  = dx*dx + dy*dy + dz*dz;
        if (d < worst){
            bd[wpos]=d; bj[wpos]=base+j;
            worst = bd[0]; wpos = 0;
            #pragma unroll
            for (int k=1;k<KNN;k++) if (bd[k] > worst){ worst = bd[k]; wpos = k; }
        }
    }
    int i = base + il;
    #pragma unroll
    for (int k=0;k<KNN;k++) g_idx1[i*KNN+k] = bj[k];
}

// ---------------- kernel 2: EdgeConv1 (warp per point) ----------------
__global__ __launch_bounds__(128) void conv1_kernel(
    const float* __restrict__ pos,
    const float* __restrict__ W1, const float* __restrict__ b1,
    const float* __restrict__ bns, const float* __restrict__ bnb,
    const float* __restrict__ W2, const float* __restrict__ b2)
{
    __shared__ float sW1f[6*64];
    __shared__ float sb1f[64];
    __shared__ float sW2[64*64];
    __shared__ float sb2[64];
    __shared__ float sH[4][KNN*64];

    int tid = threadIdx.x;
    for (int t = tid; t < 64; t += 128){
        float sc = bns[t];
        sb1f[t] = b1[t]*sc + bnb[t];    // fold BN into layer-1 affine
        sb2[t]  = b2[t];
        #pragma unroll
        for (int d=0; d<6; d++) sW1f[d*64+t] = W1[d*64+t]*sc;
    }
    for (int t = tid; t < 4096; t += 128) sW2[t] = W2[t];
    __syncthreads();

    int warp = tid >> 5, lane = tid & 31;
    int i = blockIdx.x*4 + warp;
    float xi0 = pos[i*3+0], xi1 = pos[i*3+1], xi2 = pos[i*3+2];
    float* H = sH[warp];
    int c0 = lane, c1 = lane + 32;

    float w3a = sW1f[192+c0], w4a = sW1f[256+c0], w5a = sW1f[320+c0];
    float w3b = sW1f[192+c1], w4b = sW1f[256+c1], w5b = sW1f[320+c1];
    float basea = sb1f[c0] + xi0*sW1f[c0] + xi1*sW1f[64+c0] + xi2*sW1f[128+c0];
    float baseb = sb1f[c1] + xi0*sW1f[c1] + xi1*sW1f[64+c1] + xi2*sW1f[128+c1];

    // layer 1: per-edge hidden, relu, to shared
    #pragma unroll
    for (int j=0;j<KNN;j++){
        int n = g_idx1[i*KNN+j];
        float d0 = pos[n*3+0]-xi0, d1 = pos[n*3+1]-xi1, d2 = pos[n*3+2]-xi2;
        H[j*64+c0] = fmaxf(basea + d0*w3a + d1*w4a + d2*w5a, 0.f);
        H[j*64+c1] = fmaxf(baseb + d0*w3b + d1*w4b + d2*w5b, 0.f);
    }
    __syncwarp();

    // layer 2: out[j][c] = H[j] . W2[:,c]; max over j; two column passes
    float sq = 0.f;
    #pragma unroll
    for (int p=0;p<2;p++){
        int c = lane + 32*p;
        float acc[KNN];
        #pragma unroll
        for (int j=0;j<KNN;j++) acc[j] = 0.f;
        for (int k4=0;k4<64;k4+=4){
            float q0 = sW2[(k4+0)*64+c];
            float q1 = sW2[(k4+1)*64+c];
            float q2 = sW2[(k4+2)*64+c];
            float q3 = sW2[(k4+3)*64+c];
            #pragma unroll
            for (int j=0;j<KNN;j++){
                float4 h = *(const float4*)&H[j*64+k4];
                acc[j] += h.x*q0 + h.y*q1 + h.z*q2 + h.w*q3;
            }
        }
        float m = acc[0];
        #pragma unroll
        for (int j=1;j<KNN;j++) m = fmaxf(m, acc[j]);
        m += sb2[c];                 // bias constant over j -> add after max
        g_x1[i*64+c] = m;
        sq += m*m;
    }
    #pragma unroll
    for (int o=16;o;o>>=1) sq += __shfl_xor_sync(0xffffffffu, sq, o);
    if (lane == 0) g_x1sq[i] = sq;
}

// ---------------- kernel 3: kNN in 64-d feature space ----------------
__global__ __launch_bounds__(64) void knn_feat_kernel(){
    __shared__ float Xs[128*64];
    __shared__ float Ss[128];
    int cloud = blockIdx.y, base = cloud*PTS;
    int i = base + blockIdx.x*64 + threadIdx.x;

    float xi[64];
    #pragma unroll
    for (int k=0;k<64;k+=4){
        float4 v = *(const float4*)&g_x1[i*64+k];
        xi[k]=v.x; xi[k+1]=v.y; xi[k+2]=v.z; xi[k+3]=v.w;
    }
    float bd[KNN]; int bj[KNN];
    #pragma unroll
    for (int k=0;k<KNN;k++){ bd[k]=FLT_MAX; bj[k]=i; }
    float worst = FLT_MAX; int wpos = 0;

    for (int jt=0;jt<8;jt++){
        __syncthreads();
        for (int t=threadIdx.x; t<8192; t+=64) Xs[t] = g_x1[(base+jt*128)*64 + t];
        for (int t=threadIdx.x; t<128;  t+=64) Ss[t] = g_x1sq[base+jt*128+t];
        __syncthreads();
        for (int jj=0;jj<128;jj++){
            const float4* row = (const float4*)&Xs[jj*64];
            float a0=0.f,a1=0.f,a2=0.f,a3=0.f;
            #pragma unroll
            for (int q=0;q<16;q++){
                float4 v = row[q];
                a0 += xi[q*4+0]*v.x; a1 += xi[q*4+1]*v.y;
                a2 += xi[q*4+2]*v.z; a3 += xi[q*4+3]*v.w;
            }
            // key = |xj|^2 - 2<xi,xj>  (== dist - |xi|^2, same ordering)
            float key = Ss[jj] - 2.f*((a0+a1)+(a2+a3));
            if (key < worst){
                bd[wpos]=key; bj[wpos]=base+jt*128+jj;
                worst = bd[0]; wpos = 0;
                #pragma unroll
                for (int k=1;k<KNN;k++) if (bd[k] > worst){ worst = bd[k]; wpos = k; }
            }
        }
    }
    #pragma unroll
    for (int k=0;k<KNN;k++) g_idx2[i*KNN+k] = bj[k];
}

// ---------------- kernel 4: z = x1@Wb, s = x1@(Wt-Wb)+b (conv2 decomposed) ----------------
__global__ __launch_bounds__(256) void zs_kernel(const float* __restrict__ c2W,
                                                 const float* __restrict__ c2b){
    extern __shared__ float sm4[];
    float* sW = sm4;            // 128*128
    float* sx = sm4 + 16384;    // 8 warps * 2 pts * 64
    int tid = threadIdx.x, warp = tid>>5, lane = tid&31;
    for (int t=tid; t<16384; t+=256) sW[t] = c2W[t];
    __syncthreads();
    float cbv[4];
    #pragma unroll
    for (int q=0;q<4;q++) cbv[q] = c2b[lane+32*q];

    for (int g = blockIdx.x; g < NPTS/16; g += gridDim.x){
        int i0 = g*16 + warp*2;
        float* xw = sx + warp*128;
        xw[lane]      = g_x1[i0*64 + lane];
        xw[lane+32]   = g_x1[i0*64 + 32 + lane];
        xw[64+lane]   = g_x1[(i0+1)*64 + lane];
        xw[96+lane]   = g_x1[(i0+1)*64 + 32 + lane];
        __syncwarp();
        float az0[4]={0,0,0,0}, az1[4]={0,0,0,0}, at0[4]={0,0,0,0}, at1[4]={0,0,0,0};
        for (int k=0;k<64;k++){
            float x0 = xw[k], x1v = xw[64+k];
            #pragma unroll
            for (int q=0;q<4;q++){
                int c = lane + 32*q;
                float wt = sW[k*128+c];
                float wb = sW[(k+64)*128+c];
                at0[q] += x0*wt;  az0[q] += x0*wb;
                at1[q] += x1v*wt; az1[q] += x1v*wb;
            }
        }
        #pragma unroll
        for (int q=0;q<4;q++){
            int c = lane + 32*q;
            g_z[i0*128+c]     = az0[q];
            g_s[i0*128+c]     = at0[q]-az0[q]+cbv[q];
            g_z[(i0+1)*128+c] = az1[q];
            g_s[(i0+1)*128+c] = at1[q]-az1[q]+cbv[q];
        }
        __syncwarp();
    }
}

// ---------------- kernel 5: gather-max -> x2 ----------------
__global__ __launch_bounds__(256) void gather_kernel(){
    int gw   = (blockIdx.x*blockDim.x + threadIdx.x) >> 5;  // one warp per point
    int lane = threadIdx.x & 31;
    if (gw >= NPTS) return;
    const int* idx = &g_idx2[gw*KNN];
    float4 m = make_float4(-FLT_MAX,-FLT_MAX,-FLT_MAX,-FLT_MAX);
    #pragma unroll
    for (int j=0;j<KNN;j++){
        int n = idx[j];
        float4 v = *(const float4*)&g_z[n*128 + lane*4];
        m.x = fmaxf(m.x, v.x); m.y = fmaxf(m.y, v.y);
        m.z = fmaxf(m.z, v.z); m.w = fmaxf(m.w, v.w);
    }
    float4 sv = *(const float4*)&g_s[gw*128 + lane*4];
    float4 r  = make_float4(sv.x+m.x, sv.y+m.y, sv.z+m.z, sv.w+m.w);
    *(float4*)&g_x2[gw*128 + lane*4] = r;
}

// ---------------- kernel 6: lin([x1,x2]) + global max pool ----------------
__global__ __launch_bounds__(512) void linpool_kernel(const float* __restrict__ lW,
                                                      const float* __restrict__ lb,
                                                      unsigned* __restrict__ out){
    extern __shared__ float sm6[];
    float* sW = sm6;              // 192*128
    float* sx = sm6 + 192*128;    // 16 warps * 4 pts * 192
    int tid = threadIdx.x, warp = tid>>5, lane = tid&31;
    for (int t=tid; t<192*128; t+=512) sW[t] = lW[t];
    __syncthreads();
    float lbv[4];
    #pragma unroll
    for (int q=0;q<4;q++) lbv[q] = lb[lane+32*q];

    for (int ch = blockIdx.x*16 + warp; ch < NPTS/4; ch += gridDim.x*16){
        int p0 = ch*4;                   // 4 points, same cloud (4 | 1024)
        float* xw = sx + warp*4*192;
        #pragma unroll
        for (int pt=0; pt<4; pt++){
            int p = p0 + pt;
            #pragma unroll
            for (int t6=0; t6<6; t6++){
                int t = lane + t6*32;
                xw[pt*192 + t] = (t < 64) ? g_x1[p*64 + t] : g_x2[p*128 + (t-64)];
            }
        }
        __syncwarp();
        float acc[4][4];
        #pragma unroll
        for (int pt=0;pt<4;pt++)
            #pragma unroll
            for (int q=0;q<4;q++) acc[pt][q] = 0.f;
        #pragma unroll 4
        for (int k=0;k<192;k++){
            float w0 = sW[k*128+lane],    w1 = sW[k*128+lane+32];
            float w2 = sW[k*128+lane+64], w3 = sW[k*128+lane+96];
            #pragma unroll
            for (int pt=0;pt<4;pt++){
                float xv = xw[pt*192+k];
                acc[pt][0] += xv*w0; acc[pt][1] += xv*w1;
                acc[pt][2] += xv*w2; acc[pt][3] += xv*w3;
            }
        }
        int cloud = p0 >> 10;
        #pragma unroll
        for (int q=0;q<4;q++){
            float m = fmaxf(fmaxf(acc[0][q],acc[1][q]), fmaxf(acc[2][q],acc[3][q])) + lbv[q];
            atomicMax(&out[cloud*128 + lane + 32*q], f2key(m));
        }
        __syncwarp();
    }
}

// ---------------- launch ----------------
extern "C" void kernel_launch(void* const* d_in, const int* in_sizes, int n_in,
                              void* d_out, int out_size)
{
    const float* pos  = (const float*)d_in[0];
    // d_in[1] = batch ids (layout known: contiguous clouds of 1024) — unused
    const float* c1W1 = (const float*)d_in[2];
    const float* c1b1 = (const float*)d_in[3];
    const float* bns  = (const float*)d_in[4];
    const float* bnb  = (const float*)d_in[5];
    const float* c1W2 = (const float*)d_in[6];
    const float* c1b2 = (const float*)d_in[7];
    const float* c2W  = (const float*)d_in[8];
    const float* c2b  = (const float*)d_in[9];
    const float* lW   = (const float*)d_in[10];
    const float* lb   = (const float*)d_in[11];
    unsigned* out = (unsigned*)d_out;

    const int ZS_SMEM = (16384 + 8*128) * 4;            // 69,632 B
    const int LP_SMEM = (192*128 + 16*4*192) * 4;       // 147,456 B
    cudaFuncSetAttribute(zs_kernel,      cudaFuncAttributeMaxDynamicSharedMemorySize, ZS_SMEM);
    cudaFuncSetAttribute(linpool_kernel, cudaFuncAttributeMaxDynamicSharedMemorySize, LP_SMEM);

    init_out_kernel<<<16, 256>>>(out);
    knn_pos_kernel<<<dim3(PTS/128, BATCH), 128>>>(pos);
    conv1_kernel<<<NPTS/4, 128>>>(pos, c1W1, c1b1, bns, bnb, c1W2, c1b2);
    knn_feat_kernel<<<dim3(PTS/64, BATCH), 64>>>();
    zs_kernel<<<444, 256, ZS_SMEM>>>(c2W, c2b);
    gather_kernel<<<NPTS/8, 256>>>();
    linpool_kernel<<<148, 512, LP_SMEM>>>(lW, lb, out);
    decode_out_kernel<<<16, 256>>>(out);
}

// round 3
// speedup vs baseline: 1.1172x; 1.1172x over previous
#include <cuda_runtime.h>
#include <cfloat>
#include <cstdint>

#define BATCH 32
#define PTS   1024
#define KNN   20
#define NPTS  (BATCH*PTS)

// ---------------- device scratch (no allocations allowed) ----------------
__device__ int   g_idx1[NPTS*KNN];    // kNN in pos space
__device__ float g_x1  [NPTS*64];     // conv1 output
__device__ float g_x1sq[NPTS];        // |x1|^2 per point
__device__ int   g_idx2[NPTS*KNN];    // kNN in feature space
__device__ float g_z   [NPTS*128];    // x1_j @ Wb
__device__ float g_s   [NPTS*128];    // x1_i @ (Wt-Wb) + b
__device__ float g_x2  [NPTS*128];    // conv2 output

// ordered-uint encoding for float atomicMax (handles negatives)
__device__ __forceinline__ unsigned f2key(float f){
    unsigned u = __float_as_uint(f);
    return (u & 0x80000000u) ? ~u : (u | 0x80000000u);
}
__device__ __forceinline__ float key2f(unsigned u){
    unsigned b = (u & 0x80000000u) ? (u & 0x7FFFFFFFu) : ~u;
    return __uint_as_float(b);
}

// ---------------- kernel 0/7: init + decode output ----------------
__global__ void init_out_kernel(unsigned* out){
    int t = blockIdx.x*blockDim.x + threadIdx.x;
    if (t < BATCH*128) out[t] = 0u;   // encodes -inf
}
__global__ void decode_out_kernel(unsigned* out){
    int t = blockIdx.x*blockDim.x + threadIdx.x;
    if (t < BATCH*128) out[t] = __float_as_uint(key2f(out[t]));
}

// ---------------- kernel 1: kNN in 3D position space (4-way j-split) ----------------
// block = 128 threads = 32 points x 4 splits. Each thread keeps exact top-20
// over its j-subset (j = s mod 4); branchless rank merge of 80 candidates.
__global__ __launch_bounds__(128) void knn_pos_kernel(const float* __restrict__ pos){
    __shared__ float xs[PTS], ys[PTS], zs[PTS];
    __shared__ float mk[32*80];
    __shared__ int   mi[32*80];
    int cloud = blockIdx.y;
    int base  = cloud * PTS;
    int tid = threadIdx.x;
    for (int t = tid; t < PTS; t += 128){
        xs[t] = pos[(base+t)*3+0];
        ys[t] = pos[(base+t)*3+1];
        zs[t] = pos[(base+t)*3+2];
    }
    __syncthreads();
    int p = tid >> 2, s = tid & 3;
    int il = blockIdx.x*32 + p;
    float xi = xs[il], yi = ys[il], zi = zs[il];

    float bd[KNN]; int bj[KNN];
    #pragma unroll
    for (int k=0;k<KNN;k++){ bd[k]=FLT_MAX; bj[k]=base+il; }
    float worst = FLT_MAX; int wpos = 0;

    for (int j=s; j<PTS; j+=4){
        float dx = xs[j]-xi, dy = ys[j]-yi, dz = zs[j]-zi;
        float d  = dx*dx + dy*dy + dz*dz;
        if (d < worst){
            bd[wpos]=d; bj[wpos]=base+j;
            worst = bd[0]; wpos = 0;
            #pragma unroll
            for (int k=1;k<KNN;k++) if (bd[k] > worst){ worst = bd[k]; wpos = k; }
        }
    }
    // dump candidates
    int cb = p*80, myoff = s*20;
    #pragma unroll
    for (int k=0;k<KNN;k++){ mk[cb+myoff+k]=bd[k]; mi[cb+myoff+k]=bj[k]; }
    __syncthreads();
    // rank merge: candidate at (key,pos) -> rank among 80; rank<20 wins
    int i = base + il;
    #pragma unroll
    for (int k=0;k<KNN;k++){
        float kc = bd[k]; int cpos = myoff + k;
        int rank = 0;
        for (int q=0;q<80;q++){
            float kq = mk[cb+q];
            rank += (kq < kc) || (kq == kc && q < cpos);
        }
        if (rank < KNN) g_idx1[i*KNN+rank] = bj[k];
    }
}

// ---------------- kernel 2: EdgeConv1 (warp per point) ----------------
__global__ __launch_bounds__(128) void conv1_kernel(
    const float* __restrict__ pos,
    const float* __restrict__ W1, const float* __restrict__ b1,
    const float* __restrict__ bns, const float* __restrict__ bnb,
    const float* __restrict__ W2, const float* __restrict__ b2)
{
    __shared__ float sW1f[6*64];
    __shared__ float sb1f[64];
    __shared__ float sW2[64*64];
    __shared__ float sb2[64];
    __shared__ float sH[4][KNN*64];

    int tid = threadIdx.x;
    for (int t = tid; t < 64; t += 128){
        float sc = bns[t];
        sb1f[t] = b1[t]*sc + bnb[t];    // fold BN into layer-1 affine
        sb2[t]  = b2[t];
        #pragma unroll
        for (int d=0; d<6; d++) sW1f[d*64+t] = W1[d*64+t]*sc;
    }
    for (int t = tid; t < 4096; t += 128) sW2[t] = W2[t];
    __syncthreads();

    int warp = tid >> 5, lane = tid & 31;
    int i = blockIdx.x*4 + warp;
    float xi0 = pos[i*3+0], xi1 = pos[i*3+1], xi2 = pos[i*3+2];
    float* H = sH[warp];
    int c0 = lane, c1 = lane + 32;

    float w3a = sW1f[192+c0], w4a = sW1f[256+c0], w5a = sW1f[320+c0];
    float w3b = sW1f[192+c1], w4b = sW1f[256+c1], w5b = sW1f[320+c1];
    float basea = sb1f[c0] + xi0*sW1f[c0] + xi1*sW1f[64+c0] + xi2*sW1f[128+c0];
    float baseb = sb1f[c1] + xi0*sW1f[c1] + xi1*sW1f[64+c1] + xi2*sW1f[128+c1];

    // layer 1: per-edge hidden, relu, to shared
    #pragma unroll
    for (int j=0;j<KNN;j++){
        int n = g_idx1[i*KNN+j];
        float d0 = pos[n*3+0]-xi0, d1 = pos[n*3+1]-xi1, d2 = pos[n*3+2]-xi2;
        H[j*64+c0] = fmaxf(basea + d0*w3a + d1*w4a + d2*w5a, 0.f);
        H[j*64+c1] = fmaxf(baseb + d0*w3b + d1*w4b + d2*w5b, 0.f);
    }
    __syncwarp();

    // layer 2: out[j][c] = H[j] . W2[:,c]; max over j; two column passes
    float sq = 0.f;
    #pragma unroll
    for (int p=0;p<2;p++){
        int c = lane + 32*p;
        float acc[KNN];
        #pragma unroll
        for (int j=0;j<KNN;j++) acc[j] = 0.f;
        for (int k4=0;k4<64;k4+=4){
            float q0 = sW2[(k4+0)*64+c];
            float q1 = sW2[(k4+1)*64+c];
            float q2 = sW2[(k4+2)*64+c];
            float q3 = sW2[(k4+3)*64+c];
            #pragma unroll
            for (int j=0;j<KNN;j++){
                float4 h = *(const float4*)&H[j*64+k4];
                acc[j] += h.x*q0 + h.y*q1 + h.z*q2 + h.w*q3;
            }
        }
        float m = acc[0];
        #pragma unroll
        for (int j=1;j<KNN;j++) m = fmaxf(m, acc[j]);
        m += sb2[c];                 // bias constant over j -> add after max
        g_x1[i*64+c] = m;
        sq += m*m;
    }
    #pragma unroll
    for (int o=16;o;o>>=1) sq += __shfl_xor_sync(0xffffffffu, sq, o);
    if (lane == 0) g_x1sq[i] = sq;
}

// ---------------- kernel 3: kNN in 64-d feature space (4-way j-split) ----------------
// block = 128 threads = 32 points x 4 splits; Xs tile rows padded to 68 floats.
#define XS_STRIDE 68
__global__ __launch_bounds__(128) void knn_feat_kernel(){
    __shared__ float SB[128*XS_STRIDE + 128];  // tile + Ss; merge arrays alias SB
    float* Xs = SB;
    float* Ss = SB + 128*XS_STRIDE;
    int cloud = blockIdx.y, base = cloud*PTS;
    int tid = threadIdx.x, p = tid >> 2, s = tid & 3;
    int i = base + blockIdx.x*32 + p;

    float xi[64];
    #pragma unroll
    for (int k=0;k<64;k+=4){
        float4 v = *(const float4*)&g_x1[i*64+k];
        xi[k]=v.x; xi[k+1]=v.y; xi[k+2]=v.z; xi[k+3]=v.w;
    }
    float bd[KNN]; int bj[KNN];
    #pragma unroll
    for (int k=0;k<KNN;k++){ bd[k]=FLT_MAX; bj[k]=i; }
    float worst = FLT_MAX; int wpos = 0;

    for (int jt=0;jt<8;jt++){
        __syncthreads();
        for (int t=tid; t<8192; t+=128){
            int jj = t >> 6, c = t & 63;
            Xs[jj*XS_STRIDE + c] = g_x1[(base+jt*128)*64 + t];
        }
        for (int t=tid; t<128; t+=128) Ss[t] = g_x1sq[base+jt*128+t];
        __syncthreads();
        for (int jj=s; jj<128; jj+=4){
            const float4* row = (const float4*)&Xs[jj*XS_STRIDE];
            float a0=0.f,a1=0.f,a2=0.f,a3=0.f;
            #pragma unroll
            for (int q=0;q<16;q++){
                float4 v = row[q];
                a0 += xi[q*4+0]*v.x; a1 += xi[q*4+1]*v.y;
                a2 += xi[q*4+2]*v.z; a3 += xi[q*4+3]*v.w;
            }
            // key = |xj|^2 - 2<xi,xj>  (== dist - |xi|^2, same ordering)
            float key = Ss[jj] - 2.f*((a0+a1)+(a2+a3));
            if (key < worst){
                bd[wpos]=key; bj[wpos]=base+jt*128+jj;
                worst = bd[0]; wpos = 0;
                #pragma unroll
                for (int k=1;k<KNN;k++) if (bd[k] > worst){ worst = bd[k]; wpos = k; }
            }
        }
    }
    __syncthreads();
    // merge phase: alias SB as mk[32*80] floats + mi[32*80] ints
    float* mk = SB;
    int*   mi = (int*)(SB + 32*80);
    int cb = p*80, myoff = s*20;
    #pragma unroll
    for (int k=0;k<KNN;k++){ mk[cb+myoff+k]=bd[k]; mi[cb+myoff+k]=bj[k]; }
    __syncthreads();
    #pragma unroll
    for (int k=0;k<KNN;k++){
        float kc = bd[k]; int cpos = myoff + k;
        int rank = 0;
        for (int q=0;q<80;q++){
            float kq = mk[cb+q];
            rank += (kq < kc) || (kq == kc && q < cpos);
        }
        if (rank < KNN) g_idx2[i*KNN+rank] = bj[k];
    }
}

// ---------------- kernel 4: z = x1@Wb, s = x1@(Wt-Wb)+b (conv2 decomposed) ----------------
__global__ __launch_bounds__(256) void zs_kernel(const float* __restrict__ c2W,
                                                 const float* __restrict__ c2b){
    extern __shared__ float sm4[];
    float* sW = sm4;            // 128*128
    float* sx = sm4 + 16384;    // 8 warps * 2 pts * 64
    int tid = threadIdx.x, warp = tid>>5, lane = tid&31;
    for (int t=tid; t<16384; t+=256) sW[t] = c2W[t];
    __syncthreads();
    float cbv[4];
    #pragma unroll
    for (int q=0;q<4;q++) cbv[q] = c2b[lane+32*q];

    for (int g = blockIdx.x; g < NPTS/16; g += gridDim.x){
        int i0 = g*16 + warp*2;
        float* xw = sx + warp*128;
        xw[lane]      = g_x1[i0*64 + lane];
        xw[lane+32]   = g_x1[i0*64 + 32 + lane];
        xw[64+lane]   = g_x1[(i0+1)*64 + lane];
        xw[96+lane]   = g_x1[(i0+1)*64 + 32 + lane];
        __syncwarp();
        float az0[4]={0,0,0,0}, az1[4]={0,0,0,0}, at0[4]={0,0,0,0}, at1[4]={0,0,0,0};
        for (int k=0;k<64;k++){
            float x0 = xw[k], x1v = xw[64+k];
            #pragma unroll
            for (int q=0;q<4;q++){
                int c = lane + 32*q;
                float wt = sW[k*128+c];
                float wb = sW[(k+64)*128+c];
                at0[q] += x0*wt;  az0[q] += x0*wb;
                at1[q] += x1v*wt; az1[q] += x1v*wb;
            }
        }
        #pragma unroll
        for (int q=0;q<4;q++){
            int c = lane + 32*q;
            g_z[i0*128+c]     = az0[q];
            g_s[i0*128+c]     = at0[q]-az0[q]+cbv[q];
            g_z[(i0+1)*128+c] = az1[q];
            g_s[(i0+1)*128+c] = at1[q]-az1[q]+cbv[q];
        }
        __syncwarp();
    }
}

// ---------------- kernel 5: gather-max -> x2 ----------------
__global__ __launch_bounds__(256) void gather_kernel(){
    int gw   = (blockIdx.x*blockDim.x + threadIdx.x) >> 5;  // one warp per point
    int lane = threadIdx.x & 31;
    if (gw >= NPTS) return;
    const int* idx = &g_idx2[gw*KNN];
    float4 m = make_float4(-FLT_MAX,-FLT_MAX,-FLT_MAX,-FLT_MAX);
    #pragma unroll
    for (int j=0;j<KNN;j++){
        int n = idx[j];
        float4 v = *(const float4*)&g_z[n*128 + lane*4];
        m.x = fmaxf(m.x, v.x); m.y = fmaxf(m.y, v.y);
        m.z = fmaxf(m.z, v.z); m.w = fmaxf(m.w, v.w);
    }
    float4 sv = *(const float4*)&g_s[gw*128 + lane*4];
    float4 r  = make_float4(sv.x+m.x, sv.y+m.y, sv.z+m.z, sv.w+m.w);
    *(float4*)&g_x2[gw*128 + lane*4] = r;
}

// ---------------- kernel 6: lin([x1,x2]) + global max pool ----------------
__global__ __launch_bounds__(512) void linpool_kernel(const float* __restrict__ lW,
                                                      const float* __restrict__ lb,
                                                      unsigned* __restrict__ out){
    extern __shared__ float sm6[];
    float* sW = sm6;              // 192*128
    float* sx = sm6 + 192*128;    // 16 warps * 4 pts * 192
    int tid = threadIdx.x, warp = tid>>5, lane = tid&31;
    for (int t=tid; t<192*128; t+=512) sW[t] = lW[t];
    __syncthreads();
    float lbv[4];
    #pragma unroll
    for (int q=0;q<4;q++) lbv[q] = lb[lane+32*q];

    for (int ch = blockIdx.x*16 + warp; ch < NPTS/4; ch += gridDim.x*16){
        int p0 = ch*4;                   // 4 points, same cloud (4 | 1024)
        float* xw = sx + warp*4*192;
        #pragma unroll
        for (int pt=0; pt<4; pt++){
            int p = p0 + pt;
            #pragma unroll
            for (int t6=0; t6<6; t6++){
                int t = lane + t6*32;
                xw[pt*192 + t] = (t < 64) ? g_x1[p*64 + t] : g_x2[p*128 + (t-64)];
            }
        }
        __syncwarp();
        float acc[4][4];
        #pragma unroll
        for (int pt=0;pt<4;pt++)
            #pragma unroll
            for (int q=0;q<4;q++) acc[pt][q] = 0.f;
        #pragma unroll 4
        for (int k=0;k<192;k++){
            float w0 = sW[k*128+lane],    w1 = sW[k*128+lane+32];
            float w2 = sW[k*128+lane+64], w3 = sW[k*128+lane+96];
            #pragma unroll
            for (int pt=0;pt<4;pt++){
                float xv = xw[pt*192+k];
                acc[pt][0] += xv*w0; acc[pt][1] += xv*w1;
                acc[pt][2] += xv*w2; acc[pt][3] += xv*w3;
            }
        }
        int cloud = p0 >> 10;
        #pragma unroll
        for (int q=0;q<4;q++){
            float m = fmaxf(fmaxf(acc[0][q],acc[1][q]), fmaxf(acc[2][q],acc[3][q])) + lbv[q];
            atomicMax(&out[cloud*128 + lane + 32*q], f2key(m));
        }
        __syncwarp();
    }
}

// ---------------- launch ----------------
extern "C" void kernel_launch(void* const* d_in, const int* in_sizes, int n_in,
                              void* d_out, int out_size)
{
    const float* pos  = (const float*)d_in[0];
    // d_in[1] = batch ids (layout known: contiguous clouds of 1024) — unused
    const float* c1W1 = (const float*)d_in[2];
    const float* c1b1 = (const float*)d_in[3];
    const float* bns  = (const float*)d_in[4];
    const float* bnb  = (const float*)d_in[5];
    const float* c1W2 = (const float*)d_in[6];
    const float* c1b2 = (const float*)d_in[7];
    const float* c2W  = (const float*)d_in[8];
    const float* c2b  = (const float*)d_in[9];
    const float* lW   = (const float*)d_in[10];
    const float* lb   = (const float*)d_in[11];
    unsigned* out = (unsigned*)d_out;

    const int ZS_SMEM = (16384 + 8*128) * 4;            // 69,632 B
    const int LP_SMEM = (192*128 + 16*4*192) * 4;       // 147,456 B
    cudaFuncSetAttribute(zs_kernel,      cudaFuncAttributeMaxDynamicSharedMemorySize, ZS_SMEM);
    cudaFuncSetAttribute(linpool_kernel, cudaFuncAttributeMaxDynamicSharedMemorySize, LP_SMEM);

    init_out_kernel<<<16, 256>>>(out);
    knn_pos_kernel<<<dim3(PTS/32, BATCH), 128>>>(pos);
    conv1_kernel<<<NPTS/4, 128>>>(pos, c1W1, c1b1, bns, bnb, c1W2, c1b2);
    knn_feat_kernel<<<dim3(PTS/32, BATCH), 128>>>();
    zs_kernel<<<444, 256, ZS_SMEM>>>(c2W, c2b);
    gather_kernel<<<NPTS/8, 256>>>();
    linpool_kernel<<<148, 512, LP_SMEM>>>(lW, lb, out);
    decode_out_kernel<<<16, 256>>>(out);
}